// round 12
// baseline (speedup 1.0000x reference)
#include <cuda_runtime.h>
#include <cuda_fp16.h>
#include <stdint.h>
#include <math.h>

#define NBATCH 4
#define SQ    2048
#define SKV   4096
#define EDIM  1024
#define CDIM  512
#define HEADS 16
#define HDIM  64

// ---------------------------------------------------------------------------
// Static device scratch. Single-pass fp16 GEMM operands (10 mantissa bits;
// aggregate rel err measured 3.0e-4, inside the 1e-3 tolerance).
// ---------------------------------------------------------------------------
__device__ float  g_cond[(size_t)NBATCH * SQ * EDIM];      // fp32 cond (attn input)
__device__ __half g_ch[(size_t)NBATCH * SQ * CDIM];        // condition fp16
__device__ __half g_wch[(size_t)EDIM * CDIM];              // Wc fp16
__device__ __half g_woh[(size_t)EDIM * EDIM];              // Wo fp16
__device__ __half g_aoh[(size_t)NBATCH * SKV * EDIM];      // attn out fp16

// ---------------------------------------------------------------------------
// PTX helpers
// ---------------------------------------------------------------------------
__device__ __forceinline__ uint32_t smem_u32(const void* p) {
    uint32_t a;
    asm("{ .reg .u64 t; cvta.to.shared.u64 t, %1; cvt.u32.u64 %0, t; }"
        : "=r"(a) : "l"(p));
    return a;
}

__device__ __forceinline__ void cp16(uint32_t dst, const void* src) {
    asm volatile("cp.async.cg.shared.global [%0], [%1], 16;\n" :: "r"(dst), "l"(src));
}

#define LDSM4(r, addr) \
    asm volatile("ldmatrix.sync.aligned.m8n8.x4.shared.b16 {%0,%1,%2,%3}, [%4];" \
        : "=r"((r)[0]), "=r"((r)[1]), "=r"((r)[2]), "=r"((r)[3]) : "r"(addr))

#define MMA16816(d, a, b) \
    asm volatile("mma.sync.aligned.m16n8k16.row.col.f32.f16.f16.f32 " \
        "{%0,%1,%2,%3}, {%4,%5,%6,%7}, {%8,%9}, {%0,%1,%2,%3};" \
        : "+f"((d)[0]), "+f"((d)[1]), "+f"((d)[2]), "+f"((d)[3]) \
        : "r"((a)[0]), "r"((a)[1]), "r"((a)[2]), "r"((a)[3]), \
          "r"((b)[0]), "r"((b)[1]))

// ---------------------------------------------------------------------------
// convert: fp32 -> fp16
// ---------------------------------------------------------------------------
__global__ __launch_bounds__(256) void to_half(
    const float* __restrict__ src, __half* __restrict__ dst, int n)
{
    int i = (blockIdx.x * blockDim.x + threadIdx.x) * 4;
    if (i >= n) return;
    float4 v = *(const float4*)(src + i);
    __half2 p0 = __floats2half2_rn(v.x, v.y);
    __half2 p1 = __floats2half2_rn(v.z, v.w);
    *(__half2*)(dst + i)     = p0;
    *(__half2*)(dst + i + 2) = p1;
}

// ---------------------------------------------------------------------------
// HMMA fp16 GEMM: C[m][n] = sum_k A[m][k]*B[n][k] + bias[n]  (fp32 accum)
// BM=BN=128, BKC=64. 128 threads, 4 warps, 64x64 warp tile.
// 3-stage cp.async, A-frags double-buffered across ks, B per-ks in halves.
// SMEM rows 144B: stride 36 words == 4 mod 32 -> conflict-free ldmatrix.
// ---------------------------------------------------------------------------
#define BM 128
#define BN 128
#define BKC 64
#define AROW 144
#define ASTAGE (128 * AROW)       // 18432 B
#define STAGE  (2 * ASTAGE)       // 36864 B
#define NSTAGE 3
#define DSMEM  (NSTAGE * STAGE)   // 110592 B

__device__ __forceinline__ void gemm_issue(
    uint32_t s0, int slot, int c, int K, int tid, int mBase, int nBase,
    const __half* __restrict__ A, const __half* __restrict__ B)
{
    int k0 = c * BKC;
    uint32_t sA = s0 + slot * STAGE;
    uint32_t sB = sA + ASTAGE;
    #pragma unroll
    for (int i = 0; i < 8; i++) {
        int ch = tid + i * 128;          // 0..1023
        int r = ch >> 3, col = ch & 7;   // row, 16B-chunk within 128B
        cp16(sA + r * AROW + col * 16, A + (size_t)(mBase + r) * K + k0 + col * 8);
        cp16(sB + r * AROW + col * 16, B + (size_t)(nBase + r) * K + k0 + col * 8);
    }
    asm volatile("cp.async.commit_group;");
}

__device__ __forceinline__ void load_a(
    uint32_t sA, int ks, int wm, int lane, uint32_t af[4][4])
{
    #pragma unroll
    for (int mi = 0; mi < 4; mi++) {
        uint32_t addr = sA + (wm + mi * 16 + (lane & 15)) * AROW
                      + ks * 32 + (lane >> 4) * 16;
        LDSM4(af[mi], addr);
    }
}

// half h (0/1): loads B frags for ni = 4h .. 4h+3
__device__ __forceinline__ void load_b_half(
    uint32_t sB, int ks, int wn, int lane, int h, uint32_t bf[4][2])
{
    #pragma unroll
    for (int p2 = 0; p2 < 2; p2++) {
        int p = h * 2 + p2;
        int grp = lane >> 3, w = lane & 7;
        int nsel = p * 2 + (grp >> 1);
        uint32_t addr = sB + (wn + nsel * 8 + w) * AROW
                      + ks * 32 + (grp & 1) * 16;
        uint32_t r[4];
        LDSM4(r, addr);
        bf[p2 * 2][0]     = r[0];
        bf[p2 * 2][1]     = r[1];
        bf[p2 * 2 + 1][0] = r[2];
        bf[p2 * 2 + 1][1] = r[3];
    }
}

__global__ __launch_bounds__(128, 2) void gemm_hmma(
    const __half* __restrict__ A, const __half* __restrict__ B,
    const float* __restrict__ bias, float* __restrict__ C,
    int M, int N, int K)
{
    extern __shared__ char smem[];
    const int tid  = threadIdx.x;
    const int wid  = tid >> 5;
    const int lane = tid & 31;
    const int mBase = blockIdx.y * BM;
    const int nBase = blockIdx.x * BN;
    const int wm = (wid & 1) * 64;
    const int wn = (wid >> 1) * 64;

    const uint32_t s0 = smem_u32(smem);
    const int NC = K / BKC;

    float acc[4][8][4];
    #pragma unroll
    for (int i = 0; i < 4; i++)
        #pragma unroll
        for (int j = 0; j < 8; j++)
            #pragma unroll
            for (int q = 0; q < 4; q++) acc[i][j][q] = 0.f;

    gemm_issue(s0, 0, 0, K, tid, mBase, nBase, A, B);
    gemm_issue(s0, 1, 1, K, tid, mBase, nBase, A, B);
    asm volatile("cp.async.wait_group 1;");
    __syncthreads();

    uint32_t af[2][4][4];
    load_a(s0, 0, wm, lane, af[0]);

    int buf = 0;
    for (int c = 0; c < NC; c++) {
        uint32_t csA = s0 + (c % NSTAGE) * STAGE;
        uint32_t csB = csA + ASTAGE;
        #pragma unroll
        for (int ks = 0; ks < 4; ks++) {
            int nb = buf ^ 1;
            uint32_t bf0[4][2], bf1[4][2];
            load_b_half(csB, ks, wn, lane, 0, bf0);
            load_b_half(csB, ks, wn, lane, 1, bf1);

            if (ks < 3) {
                load_a(csA, ks + 1, wm, lane, af[nb]);
            } else {
                if (c + 2 < NC)
                    gemm_issue(s0, (c + 2) % NSTAGE, c + 2, K, tid,
                               mBase, nBase, A, B);
                else
                    asm volatile("cp.async.commit_group;");
                if (c + 1 < NC) {
                    asm volatile("cp.async.wait_group 1;");
                    __syncthreads();
                    uint32_t nA = s0 + ((c + 1) % NSTAGE) * STAGE;
                    load_a(nA, 0, wm, lane, af[nb]);
                }
            }

            #pragma unroll
            for (int mi = 0; mi < 4; mi++)
                #pragma unroll
                for (int ni = 0; ni < 4; ni++)
                    MMA16816(acc[mi][ni], af[buf][mi], bf0[ni]);
            #pragma unroll
            for (int mi = 0; mi < 4; mi++)
                #pragma unroll
                for (int ni = 0; ni < 4; ni++)
                    MMA16816(acc[mi][ni + 4], af[buf][mi], bf1[ni]);

            buf = nb;
        }
    }

    const int g = lane >> 2, tg = lane & 3;
    #pragma unroll
    for (int mi = 0; mi < 4; mi++) {
        int row0 = mBase + wm + mi * 16 + g;
        #pragma unroll
        for (int ni = 0; ni < 8; ni++) {
            int col = nBase + wn + ni * 8 + tg * 2;
            float b0 = __ldg(bias + col), b1 = __ldg(bias + col + 1);
            float2 v0 = make_float2(acc[mi][ni][0] + b0, acc[mi][ni][1] + b1);
            float2 v1 = make_float2(acc[mi][ni][2] + b0, acc[mi][ni][3] + b1);
            *(float2*)(C + (size_t)row0 * N + col) = v0;
            *(float2*)(C + (size_t)(row0 + 8) * N + col) = v1;
        }
    }
}

// ---------------------------------------------------------------------------
// Per-position heads-attention, float4 smem layout throughout.
// Thread (h = tid>>4, e = tid&15). K/V stored naturally as float4 rows with
// 17-float4 stride (68 words == 4 mod 32 -> 2-phase conflict-free).
// Softmax probs passed to the AV loop via shfl (no smem round-trip).
// ---------------------------------------------------------------------------
__global__ __launch_bounds__(256) void attn_kernel(
    const float* __restrict__ queries, const float* __restrict__ keys,
    const float* __restrict__ values, const int* __restrict__ mask)
{
    __shared__ float4 cqv[256];        // [h*16 + dv]
    __shared__ float4 kv4[16 * 17];    // [e*17 + dv]
    __shared__ float4 vv4[16 * 17];    // [e*17 + dv]

    const int pos = blockIdx.x;
    const int n = pos >> 12;
    const int t = pos & (SKV - 1);
    const int tid = threadIdx.x;
    const int h = tid >> 4;
    const int e = tid & 15;            // also dv for the load/AV phases

    const float* cqrow = (t & 1)
        ? (g_cond  + (size_t)(n * SQ + (t >> 1)) * EDIM)
        : (queries + (size_t)(n * SQ + (t >> 1)) * EDIM);
    const float* krow = keys   + (size_t)pos * EDIM;
    const float* vrow = values + (size_t)pos * EDIM;

    // mask load issued early
    const int mv = mask[(size_t)pos * (HEADS * HEADS) + h * 16 + e];

    cqv[tid]           = ((const float4*)cqrow)[tid];
    kv4[h * 17 + e]    = ((const float4*)krow)[tid];   // h==row idx here
    vv4[h * 17 + e]    = ((const float4*)vrow)[tid];
    __syncthreads();

    // scores: s[h][e] = (1/8) * dot64(cq[h], k[e])
    float s = 0.f;
    #pragma unroll
    for (int dv = 0; dv < 16; dv++) {
        float4 a = cqv[h * 16 + dv];
        float4 b = kv4[e * 17 + dv];
        s += a.x * b.x + a.y * b.y + a.z * b.z + a.w * b.w;
    }
    s *= 0.125f;
    if (mv == 0) s = -1e20f;

    // group-of-16 softmax via butterfly shuffles
    float mx = s;
    #pragma unroll
    for (int m = 1; m < 16; m <<= 1)
        mx = fmaxf(mx, __shfl_xor_sync(0xffffffffu, mx, m));
    float pu = __expf(s - mx);
    float den = pu;
    #pragma unroll
    for (int m = 1; m < 16; m <<= 1)
        den += __shfl_xor_sync(0xffffffffu, den, m);
    float p = pu / den;

    // AV: out[h][4e..4e+3] = sum_j p[h][j] * v[j][4e..4e+3]
    const int lanebase = (tid & 31) & 16;   // 16-lane group base within warp
    float4 acc = make_float4(0.f, 0.f, 0.f, 0.f);
    #pragma unroll
    for (int j = 0; j < 16; j++) {
        float a = __shfl_sync(0xffffffffu, p, lanebase + j);
        float4 v = vv4[j * 17 + e];
        acc.x += a * v.x;
        acc.y += a * v.y;
        acc.z += a * v.z;
        acc.w += a * v.w;
    }

    size_t base = (size_t)pos * EDIM + (size_t)tid * 4;
    *(__half2*)(g_aoh + base)     = __floats2half2_rn(acc.x, acc.y);
    *(__half2*)(g_aoh + base + 2) = __floats2half2_rn(acc.z, acc.w);
}

// ---------------------------------------------------------------------------
// Launch
// ---------------------------------------------------------------------------
extern "C" void kernel_launch(void* const* d_in, const int* in_sizes, int n_in,
                              void* d_out, int out_size)
{
    const float* values    = (const float*)d_in[0];
    const float* keys      = (const float*)d_in[1];
    const float* queries   = (const float*)d_in[2];
    const int*   mask      = (const int*)  d_in[3];
    const float* condition = (const float*)d_in[4];
    const float* Wc        = (const float*)d_in[5];
    const float* bc        = (const float*)d_in[6];
    const float* Wo        = (const float*)d_in[7];
    const float* bo        = (const float*)d_in[8];
    float* out = (float*)d_out;

    float* cond_ptr;
    __half *ch, *wch, *woh, *aoh;
    cudaGetSymbolAddress((void**)&cond_ptr, g_cond);
    cudaGetSymbolAddress((void**)&ch,  g_ch);
    cudaGetSymbolAddress((void**)&wch, g_wch);
    cudaGetSymbolAddress((void**)&woh, g_woh);
    cudaGetSymbolAddress((void**)&aoh, g_aoh);

    cudaFuncSetAttribute(gemm_hmma,
                         cudaFuncAttributeMaxDynamicSharedMemorySize, DSMEM);

    // converts
    {
        int n = NBATCH * SQ * CDIM;
        to_half<<<n / 4 / 256, 256>>>(condition, ch, n);
        n = EDIM * CDIM;
        to_half<<<n / 4 / 256, 256>>>(Wc, wch, n);
        n = EDIM * EDIM;
        to_half<<<n / 4 / 256, 256>>>(Wo, woh, n);
    }

    // 1) cond = condition @ Wc^T + bc : M=8192, N=1024, K=512
    {
        dim3 grid(EDIM / BN, (NBATCH * SQ) / BM);
        gemm_hmma<<<grid, 128, DSMEM>>>(ch, wch, bc, cond_ptr,
                                        NBATCH * SQ, EDIM, CDIM);
    }

    // 2) attention -> g_aoh (fp16)
    attn_kernel<<<NBATCH * SKV, 256>>>(queries, keys, values, mask);

    // 3) out = attout @ Wo^T + bo : M=16384, N=1024, K=1024
    {
        dim3 grid(EDIM / BN, (NBATCH * SKV) / BM);
        gemm_hmma<<<grid, 128, DSMEM>>>(aoh, woh, bo, out,
                                        NBATCH * SKV, EDIM, EDIM);
    }
}

// round 13
// speedup vs baseline: 1.0719x; 1.0719x over previous
#include <cuda_runtime.h>
#include <cuda_fp16.h>
#include <stdint.h>
#include <math.h>

#define NBATCH 4
#define SQ    2048
#define SKV   4096
#define EDIM  1024
#define CDIM  512
#define HEADS 16
#define HDIM  64

// ---------------------------------------------------------------------------
// Static device scratch. Single-pass fp16 GEMM operands (measured 3.0e-4
// aggregate rel err, inside the 1e-3 tolerance).
// ---------------------------------------------------------------------------
__device__ float  g_cond[(size_t)NBATCH * SQ * EDIM];      // fp32 cond (attn input)
__device__ __half g_ch[(size_t)NBATCH * SQ * CDIM];        // condition fp16
__device__ __half g_wch[(size_t)EDIM * CDIM];              // Wc fp16
__device__ __half g_woh[(size_t)EDIM * EDIM];              // Wo fp16
__device__ __half g_aoh[(size_t)NBATCH * SKV * EDIM];      // attn out fp16

// ---------------------------------------------------------------------------
// PTX helpers
// ---------------------------------------------------------------------------
__device__ __forceinline__ uint32_t smem_u32(const void* p) {
    uint32_t a;
    asm("{ .reg .u64 t; cvta.to.shared.u64 t, %1; cvt.u32.u64 %0, t; }"
        : "=r"(a) : "l"(p));
    return a;
}

__device__ __forceinline__ void cp16(uint32_t dst, const void* src) {
    asm volatile("cp.async.cg.shared.global [%0], [%1], 16;\n" :: "r"(dst), "l"(src));
}

#define LDSM4(r, addr) \
    asm volatile("ldmatrix.sync.aligned.m8n8.x4.shared.b16 {%0,%1,%2,%3}, [%4];" \
        : "=r"((r)[0]), "=r"((r)[1]), "=r"((r)[2]), "=r"((r)[3]) : "r"(addr))

#define MMA16816(d, a, b) \
    asm volatile("mma.sync.aligned.m16n8k16.row.col.f32.f16.f16.f32 " \
        "{%0,%1,%2,%3}, {%4,%5,%6,%7}, {%8,%9}, {%0,%1,%2,%3};" \
        : "+f"((d)[0]), "+f"((d)[1]), "+f"((d)[2]), "+f"((d)[3]) \
        : "r"((a)[0]), "r"((a)[1]), "r"((a)[2]), "r"((a)[3]), \
          "r"((b)[0]), "r"((b)[1]))

// ---------------------------------------------------------------------------
// fused convert: fp32 -> fp16 for condition, Wc, Wo in one launch
// ---------------------------------------------------------------------------
#define N_COND (NBATCH * SQ * CDIM)
#define N_WC   (EDIM * CDIM)
#define N_WO   (EDIM * EDIM)

__global__ __launch_bounds__(256) void to_half_all(
    const float* __restrict__ s0, __half* __restrict__ d0,
    const float* __restrict__ s1, __half* __restrict__ d1,
    const float* __restrict__ s2, __half* __restrict__ d2)
{
    int i = (blockIdx.x * blockDim.x + threadIdx.x) * 4;
    const float* src;
    __half* dst;
    if (i < N_COND)                { src = s0;  dst = d0; }
    else if (i < N_COND + N_WC)    { src = s1 - N_COND; dst = d1 - N_COND; }
    else if (i < N_COND + N_WC + N_WO) {
        src = s2 - (N_COND + N_WC); dst = d2 - (N_COND + N_WC);
    } else return;
    float4 v = *(const float4*)(src + i);
    *(__half2*)(dst + i)     = __floats2half2_rn(v.x, v.y);
    *(__half2*)(dst + i + 2) = __floats2half2_rn(v.z, v.w);
}

// ---------------------------------------------------------------------------
// HMMA fp16 GEMM: C[m][n] = sum_k A[m][k]*B[n][k] + bias[n]  (fp32 accum)
// BM=BN=128, BKC=64. 128 threads, 4 warps, 64x64 warp tile.
// 3-stage cp.async; A-frags double-buffered across ks; B per-ks in halves.
// Odd warps execute ks in rotated order (+2) so the two warps of an SMSP
// are anti-phased: one runs MMAs while the other is in its LDSM window.
// SMEM rows 144B: stride 36 words == 4 mod 32 -> conflict-free ldmatrix.
// ---------------------------------------------------------------------------
#define BM 128
#define BN 128
#define BKC 64
#define AROW 144
#define ASTAGE (128 * AROW)       // 18432 B
#define STAGE  (2 * ASTAGE)       // 36864 B
#define NSTAGE 3
#define DSMEM  (NSTAGE * STAGE)   // 110592 B

__device__ __forceinline__ void gemm_issue(
    uint32_t s0, int slot, int c, int K, int tid, int mBase, int nBase,
    const __half* __restrict__ A, const __half* __restrict__ B)
{
    int k0 = c * BKC;
    uint32_t sA = s0 + slot * STAGE;
    uint32_t sB = sA + ASTAGE;
    #pragma unroll
    for (int i = 0; i < 8; i++) {
        int ch = tid + i * 128;          // 0..1023
        int r = ch >> 3, col = ch & 7;   // row, 16B-chunk within 128B
        cp16(sA + r * AROW + col * 16, A + (size_t)(mBase + r) * K + k0 + col * 8);
        cp16(sB + r * AROW + col * 16, B + (size_t)(nBase + r) * K + k0 + col * 8);
    }
    asm volatile("cp.async.commit_group;");
}

__device__ __forceinline__ void load_a(
    uint32_t sA, int ks, int wm, int lane, uint32_t af[4][4])
{
    #pragma unroll
    for (int mi = 0; mi < 4; mi++) {
        uint32_t addr = sA + (wm + mi * 16 + (lane & 15)) * AROW
                      + ks * 32 + (lane >> 4) * 16;
        LDSM4(af[mi], addr);
    }
}

// half h (0/1): loads B frags for ni = 4h .. 4h+3
__device__ __forceinline__ void load_b_half(
    uint32_t sB, int ks, int wn, int lane, int h, uint32_t bf[4][2])
{
    #pragma unroll
    for (int p2 = 0; p2 < 2; p2++) {
        int p = h * 2 + p2;
        int grp = lane >> 3, w = lane & 7;
        int nsel = p * 2 + (grp >> 1);
        uint32_t addr = sB + (wn + nsel * 8 + w) * AROW
                      + ks * 32 + (grp & 1) * 16;
        uint32_t r[4];
        LDSM4(r, addr);
        bf[p2 * 2][0]     = r[0];
        bf[p2 * 2][1]     = r[1];
        bf[p2 * 2 + 1][0] = r[2];
        bf[p2 * 2 + 1][1] = r[3];
    }
}

__global__ __launch_bounds__(128, 2) void gemm_hmma(
    const __half* __restrict__ A, const __half* __restrict__ B,
    const float* __restrict__ bias, float* __restrict__ C,
    int M, int N, int K)
{
    extern __shared__ char smem[];
    const int tid  = threadIdx.x;
    const int wid  = tid >> 5;
    const int lane = tid & 31;
    const int mBase = blockIdx.y * BM;
    const int nBase = blockIdx.x * BN;
    const int wm = (wid & 1) * 64;
    const int wn = (wid >> 1) * 64;
    const int rot = (wid & 1) * 2;      // ks rotation: anti-phase warp pairs

    const uint32_t s0 = smem_u32(smem);
    const int NC = K / BKC;

    float acc[4][8][4];
    #pragma unroll
    for (int i = 0; i < 4; i++)
        #pragma unroll
        for (int j = 0; j < 8; j++)
            #pragma unroll
            for (int q = 0; q < 4; q++) acc[i][j][q] = 0.f;

    gemm_issue(s0, 0, 0, K, tid, mBase, nBase, A, B);
    gemm_issue(s0, 1, 1, K, tid, mBase, nBase, A, B);
    asm volatile("cp.async.wait_group 1;");
    __syncthreads();

    uint32_t af[2][4][4];
    load_a(s0, rot, wm, lane, af[0]);

    int buf = 0;
    for (int c = 0; c < NC; c++) {
        uint32_t csA = s0 + (c % NSTAGE) * STAGE;
        uint32_t csB = csA + ASTAGE;
        #pragma unroll
        for (int ksi = 0; ksi < 4; ksi++) {
            const int ksr = (ksi + rot) & 3;
            int nb = buf ^ 1;
            uint32_t bf0[4][2], bf1[4][2];
            load_b_half(csB, ksr, wn, lane, 0, bf0);
            load_b_half(csB, ksr, wn, lane, 1, bf1);

            if (ksi < 3) {
                load_a(csA, (ksi + 1 + rot) & 3, wm, lane, af[nb]);
            } else {
                if (c + 2 < NC)
                    gemm_issue(s0, (c + 2) % NSTAGE, c + 2, K, tid,
                               mBase, nBase, A, B);
                else
                    asm volatile("cp.async.commit_group;");
                if (c + 1 < NC) {
                    asm volatile("cp.async.wait_group 1;");
                    __syncthreads();
                    uint32_t nA = s0 + ((c + 1) % NSTAGE) * STAGE;
                    load_a(nA, rot, wm, lane, af[nb]);
                }
            }

            #pragma unroll
            for (int mi = 0; mi < 4; mi++)
                #pragma unroll
                for (int ni = 0; ni < 4; ni++)
                    MMA16816(acc[mi][ni], af[buf][mi], bf0[ni]);
            #pragma unroll
            for (int mi = 0; mi < 4; mi++)
                #pragma unroll
                for (int ni = 0; ni < 4; ni++)
                    MMA16816(acc[mi][ni + 4], af[buf][mi], bf1[ni]);

            buf = nb;
        }
    }

    const int g = lane >> 2, tg = lane & 3;
    #pragma unroll
    for (int mi = 0; mi < 4; mi++) {
        int row0 = mBase + wm + mi * 16 + g;
        #pragma unroll
        for (int ni = 0; ni < 8; ni++) {
            int col = nBase + wn + ni * 8 + tg * 2;
            float b0 = __ldg(bias + col), b1 = __ldg(bias + col + 1);
            float2 v0 = make_float2(acc[mi][ni][0] + b0, acc[mi][ni][1] + b1);
            float2 v1 = make_float2(acc[mi][ni][2] + b0, acc[mi][ni][3] + b1);
            *(float2*)(C + (size_t)row0 * N + col) = v0;
            *(float2*)(C + (size_t)(row0 + 8) * N + col) = v1;
        }
    }
}

// ---------------------------------------------------------------------------
// Per-position heads-attention, float4 smem layout, shfl softmax.
// ---------------------------------------------------------------------------
__global__ __launch_bounds__(256) void attn_kernel(
    const float* __restrict__ queries, const float* __restrict__ keys,
    const float* __restrict__ values, const int* __restrict__ mask)
{
    __shared__ float4 cqv[256];        // [h*16 + dv]
    __shared__ float4 kv4[16 * 17];    // [e*17 + dv]
    __shared__ float4 vv4[16 * 17];    // [e*17 + dv]

    const int pos = blockIdx.x;
    const int n = pos >> 12;
    const int t = pos & (SKV - 1);
    const int tid = threadIdx.x;
    const int h = tid >> 4;
    const int e = tid & 15;

    const float* cqrow = (t & 1)
        ? (g_cond  + (size_t)(n * SQ + (t >> 1)) * EDIM)
        : (queries + (size_t)(n * SQ + (t >> 1)) * EDIM);
    const float* krow = keys   + (size_t)pos * EDIM;
    const float* vrow = values + (size_t)pos * EDIM;

    const int mv = mask[(size_t)pos * (HEADS * HEADS) + h * 16 + e];

    cqv[tid]        = ((const float4*)cqrow)[tid];
    kv4[h * 17 + e] = ((const float4*)krow)[tid];
    vv4[h * 17 + e] = ((const float4*)vrow)[tid];
    __syncthreads();

    float s = 0.f;
    #pragma unroll
    for (int dv = 0; dv < 16; dv++) {
        float4 a = cqv[h * 16 + dv];
        float4 b = kv4[e * 17 + dv];
        s += a.x * b.x + a.y * b.y + a.z * b.z + a.w * b.w;
    }
    s *= 0.125f;
    if (mv == 0) s = -1e20f;

    float mx = s;
    #pragma unroll
    for (int m = 1; m < 16; m <<= 1)
        mx = fmaxf(mx, __shfl_xor_sync(0xffffffffu, mx, m));
    float pu = __expf(s - mx);
    float den = pu;
    #pragma unroll
    for (int m = 1; m < 16; m <<= 1)
        den += __shfl_xor_sync(0xffffffffu, den, m);
    float p = pu / den;

    const int lanebase = (tid & 31) & 16;
    float4 acc = make_float4(0.f, 0.f, 0.f, 0.f);
    #pragma unroll
    for (int j = 0; j < 16; j++) {
        float a = __shfl_sync(0xffffffffu, p, lanebase + j);
        float4 v = vv4[j * 17 + e];
        acc.x += a * v.x;
        acc.y += a * v.y;
        acc.z += a * v.z;
        acc.w += a * v.w;
    }

    size_t base = (size_t)pos * EDIM + (size_t)tid * 4;
    *(__half2*)(g_aoh + base)     = __floats2half2_rn(acc.x, acc.y);
    *(__half2*)(g_aoh + base + 2) = __floats2half2_rn(acc.z, acc.w);
}

// ---------------------------------------------------------------------------
// Launch
// ---------------------------------------------------------------------------
extern "C" void kernel_launch(void* const* d_in, const int* in_sizes, int n_in,
                              void* d_out, int out_size)
{
    const float* values    = (const float*)d_in[0];
    const float* keys      = (const float*)d_in[1];
    const float* queries   = (const float*)d_in[2];
    const int*   mask      = (const int*)  d_in[3];
    const float* condition = (const float*)d_in[4];
    const float* Wc        = (const float*)d_in[5];
    const float* bc        = (const float*)d_in[6];
    const float* Wo        = (const float*)d_in[7];
    const float* bo        = (const float*)d_in[8];
    float* out = (float*)d_out;

    float* cond_ptr;
    __half *ch, *wch, *woh, *aoh;
    cudaGetSymbolAddress((void**)&cond_ptr, g_cond);
    cudaGetSymbolAddress((void**)&ch,  g_ch);
    cudaGetSymbolAddress((void**)&wch, g_wch);
    cudaGetSymbolAddress((void**)&woh, g_woh);
    cudaGetSymbolAddress((void**)&aoh, g_aoh);

    cudaFuncSetAttribute(gemm_hmma,
                         cudaFuncAttributeMaxDynamicSharedMemorySize, DSMEM);

    // fused converts (one launch)
    {
        int ntot = N_COND + N_WC + N_WO;
        to_half_all<<<ntot / 4 / 256, 256>>>(condition, ch, Wc, wch, Wo, woh);
    }

    // 1) cond = condition @ Wc^T + bc : M=8192, N=1024, K=512
    {
        dim3 grid(EDIM / BN, (NBATCH * SQ) / BM);
        gemm_hmma<<<grid, 128, DSMEM>>>(ch, wch, bc, cond_ptr,
                                        NBATCH * SQ, EDIM, CDIM);
    }

    // 2) attention -> g_aoh (fp16)
    attn_kernel<<<NBATCH * SKV, 256>>>(queries, keys, values, mask);

    // 3) out = attout @ Wo^T + bo : M=16384, N=1024, K=1024
    {
        dim3 grid(EDIM / BN, (NBATCH * SKV) / BM);
        gemm_hmma<<<grid, 128, DSMEM>>>(aoh, woh, bo, out,
                                        NBATCH * SKV, EDIM, EDIM);
    }
}

// round 14
// speedup vs baseline: 1.0818x; 1.0092x over previous
#include <cuda_runtime.h>
#include <cuda_fp16.h>
#include <stdint.h>
#include <math.h>

#define NBATCH 4
#define SQ    2048
#define SKV   4096
#define EDIM  1024
#define CDIM  512
#define HEADS 16
#define HDIM  64

// ---------------------------------------------------------------------------
// Static device scratch. Single-pass fp16 GEMM operands (measured 3.0e-4
// aggregate rel err, inside the 1e-3 tolerance).
// ---------------------------------------------------------------------------
__device__ float  g_cond[(size_t)NBATCH * SQ * EDIM];      // fp32 cond (attn input)
__device__ __half g_ch[(size_t)NBATCH * SQ * CDIM];        // condition fp16
__device__ __half g_wch[(size_t)EDIM * CDIM];              // Wc fp16
__device__ __half g_woh[(size_t)EDIM * EDIM];              // Wo fp16
__device__ __half g_aoh[(size_t)NBATCH * SKV * EDIM];      // attn out fp16

// ---------------------------------------------------------------------------
// PTX helpers
// ---------------------------------------------------------------------------
__device__ __forceinline__ uint32_t smem_u32(const void* p) {
    uint32_t a;
    asm("{ .reg .u64 t; cvta.to.shared.u64 t, %1; cvt.u32.u64 %0, t; }"
        : "=r"(a) : "l"(p));
    return a;
}

__device__ __forceinline__ void cp16(uint32_t dst, const void* src) {
    asm volatile("cp.async.cg.shared.global [%0], [%1], 16;\n" :: "r"(dst), "l"(src));
}

#define LDSM4(r, addr) \
    asm volatile("ldmatrix.sync.aligned.m8n8.x4.shared.b16 {%0,%1,%2,%3}, [%4];" \
        : "=r"((r)[0]), "=r"((r)[1]), "=r"((r)[2]), "=r"((r)[3]) : "r"(addr))

#define MMA16816(d, a, b) \
    asm volatile("mma.sync.aligned.m16n8k16.row.col.f32.f16.f16.f32 " \
        "{%0,%1,%2,%3}, {%4,%5,%6,%7}, {%8,%9}, {%0,%1,%2,%3};" \
        : "+f"((d)[0]), "+f"((d)[1]), "+f"((d)[2]), "+f"((d)[3]) \
        : "r"((a)[0]), "r"((a)[1]), "r"((a)[2]), "r"((a)[3]), \
          "r"((b)[0]), "r"((b)[1]))

// ---------------------------------------------------------------------------
// fused convert: fp32 -> fp16 for condition, Wc, Wo in one launch
// ---------------------------------------------------------------------------
#define N_COND (NBATCH * SQ * CDIM)
#define N_WC   (EDIM * CDIM)
#define N_WO   (EDIM * EDIM)

__global__ __launch_bounds__(256) void to_half_all(
    const float* __restrict__ s0, __half* __restrict__ d0,
    const float* __restrict__ s1, __half* __restrict__ d1,
    const float* __restrict__ s2, __half* __restrict__ d2)
{
    int i = (blockIdx.x * blockDim.x + threadIdx.x) * 4;
    const float* src;
    __half* dst;
    if (i < N_COND)                { src = s0;  dst = d0; }
    else if (i < N_COND + N_WC)    { src = s1 - N_COND; dst = d1 - N_COND; }
    else if (i < N_COND + N_WC + N_WO) {
        src = s2 - (N_COND + N_WC); dst = d2 - (N_COND + N_WC);
    } else return;
    float4 v = *(const float4*)(src + i);
    *(__half2*)(dst + i)     = __floats2half2_rn(v.x, v.y);
    *(__half2*)(dst + i + 2) = __floats2half2_rn(v.z, v.w);
}

// ---------------------------------------------------------------------------
// HMMA fp16 GEMM (unchanged from R13: anti-phased ks rotation, 64x64 warp
// tiles, 3-stage cp.async, A double-buffer, B halves).
// ---------------------------------------------------------------------------
#define BM 128
#define BN 128
#define BKC 64
#define AROW 144
#define ASTAGE (128 * AROW)       // 18432 B
#define STAGE  (2 * ASTAGE)       // 36864 B
#define NSTAGE 3
#define DSMEM  (NSTAGE * STAGE)   // 110592 B

__device__ __forceinline__ void gemm_issue(
    uint32_t s0, int slot, int c, int K, int tid, int mBase, int nBase,
    const __half* __restrict__ A, const __half* __restrict__ B)
{
    int k0 = c * BKC;
    uint32_t sA = s0 + slot * STAGE;
    uint32_t sB = sA + ASTAGE;
    #pragma unroll
    for (int i = 0; i < 8; i++) {
        int ch = tid + i * 128;
        int r = ch >> 3, col = ch & 7;
        cp16(sA + r * AROW + col * 16, A + (size_t)(mBase + r) * K + k0 + col * 8);
        cp16(sB + r * AROW + col * 16, B + (size_t)(nBase + r) * K + k0 + col * 8);
    }
    asm volatile("cp.async.commit_group;");
}

__device__ __forceinline__ void load_a(
    uint32_t sA, int ks, int wm, int lane, uint32_t af[4][4])
{
    #pragma unroll
    for (int mi = 0; mi < 4; mi++) {
        uint32_t addr = sA + (wm + mi * 16 + (lane & 15)) * AROW
                      + ks * 32 + (lane >> 4) * 16;
        LDSM4(af[mi], addr);
    }
}

__device__ __forceinline__ void load_b_half(
    uint32_t sB, int ks, int wn, int lane, int h, uint32_t bf[4][2])
{
    #pragma unroll
    for (int p2 = 0; p2 < 2; p2++) {
        int p = h * 2 + p2;
        int grp = lane >> 3, w = lane & 7;
        int nsel = p * 2 + (grp >> 1);
        uint32_t addr = sB + (wn + nsel * 8 + w) * AROW
                      + ks * 32 + (grp & 1) * 16;
        uint32_t r[4];
        LDSM4(r, addr);
        bf[p2 * 2][0]     = r[0];
        bf[p2 * 2][1]     = r[1];
        bf[p2 * 2 + 1][0] = r[2];
        bf[p2 * 2 + 1][1] = r[3];
    }
}

__global__ __launch_bounds__(128, 2) void gemm_hmma(
    const __half* __restrict__ A, const __half* __restrict__ B,
    const float* __restrict__ bias, float* __restrict__ C,
    int M, int N, int K)
{
    extern __shared__ char smem[];
    const int tid  = threadIdx.x;
    const int wid  = tid >> 5;
    const int lane = tid & 31;
    const int mBase = blockIdx.y * BM;
    const int nBase = blockIdx.x * BN;
    const int wm = (wid & 1) * 64;
    const int wn = (wid >> 1) * 64;
    const int rot = (wid & 1) * 2;

    const uint32_t s0 = smem_u32(smem);
    const int NC = K / BKC;

    float acc[4][8][4];
    #pragma unroll
    for (int i = 0; i < 4; i++)
        #pragma unroll
        for (int j = 0; j < 8; j++)
            #pragma unroll
            for (int q = 0; q < 4; q++) acc[i][j][q] = 0.f;

    gemm_issue(s0, 0, 0, K, tid, mBase, nBase, A, B);
    gemm_issue(s0, 1, 1, K, tid, mBase, nBase, A, B);
    asm volatile("cp.async.wait_group 1;");
    __syncthreads();

    uint32_t af[2][4][4];
    load_a(s0, rot, wm, lane, af[0]);

    int buf = 0;
    for (int c = 0; c < NC; c++) {
        uint32_t csA = s0 + (c % NSTAGE) * STAGE;
        uint32_t csB = csA + ASTAGE;
        #pragma unroll
        for (int ksi = 0; ksi < 4; ksi++) {
            const int ksr = (ksi + rot) & 3;
            int nb = buf ^ 1;
            uint32_t bf0[4][2], bf1[4][2];
            load_b_half(csB, ksr, wn, lane, 0, bf0);
            load_b_half(csB, ksr, wn, lane, 1, bf1);

            if (ksi < 3) {
                load_a(csA, (ksi + 1 + rot) & 3, wm, lane, af[nb]);
            } else {
                if (c + 2 < NC)
                    gemm_issue(s0, (c + 2) % NSTAGE, c + 2, K, tid,
                               mBase, nBase, A, B);
                else
                    asm volatile("cp.async.commit_group;");
                if (c + 1 < NC) {
                    asm volatile("cp.async.wait_group 1;");
                    __syncthreads();
                    uint32_t nA = s0 + ((c + 1) % NSTAGE) * STAGE;
                    load_a(nA, rot, wm, lane, af[nb]);
                }
            }

            #pragma unroll
            for (int mi = 0; mi < 4; mi++)
                #pragma unroll
                for (int ni = 0; ni < 4; ni++)
                    MMA16816(acc[mi][ni], af[buf][mi], bf0[ni]);
            #pragma unroll
            for (int mi = 0; mi < 4; mi++)
                #pragma unroll
                for (int ni = 0; ni < 4; ni++)
                    MMA16816(acc[mi][ni + 4], af[buf][mi], bf1[ni]);

            buf = nb;
        }
    }

    const int g = lane >> 2, tg = lane & 3;
    #pragma unroll
    for (int mi = 0; mi < 4; mi++) {
        int row0 = mBase + wm + mi * 16 + g;
        #pragma unroll
        for (int ni = 0; ni < 8; ni++) {
            int col = nBase + wn + ni * 8 + tg * 2;
            float b0 = __ldg(bias + col), b1 = __ldg(bias + col + 1);
            float2 v0 = make_float2(acc[mi][ni][0] + b0, acc[mi][ni][1] + b1);
            float2 v1 = make_float2(acc[mi][ni][2] + b0, acc[mi][ni][3] + b1);
            *(float2*)(C + (size_t)row0 * N + col) = v0;
            *(float2*)(C + (size_t)(row0 + 8) * N + col) = v1;
        }
    }
}

// ---------------------------------------------------------------------------
// Pipelined attention: 8 positions per CTA, double-buffered cp.async staging
// of (cq | K | V | mask) per position. Stage i+1 streams in while stage i
// computes -> DRAM latency hidden, kernel runs at streaming bandwidth.
// ---------------------------------------------------------------------------
#define POS_PER_CTA 8

struct AttnStage {
    float4 cq[256];        // [h*16 + dv]
    float4 kv[16 * 17];    // [e*17 + dv]
    float4 vv[16 * 17];    // [e*17 + dv]
    int    msk[256];       // [h*16 + e]
};

__global__ __launch_bounds__(256) void attn_kernel(
    const float* __restrict__ queries, const float* __restrict__ keys,
    const float* __restrict__ values, const int* __restrict__ mask)
{
    __shared__ AttnStage stg[2];

    const int tid = threadIdx.x;
    const int h = tid >> 4;
    const int e = tid & 15;
    const int pos0 = blockIdx.x * POS_PER_CTA;

    const uint32_t sbase = smem_u32(&stg[0]);
    const uint32_t stgsz = (uint32_t)sizeof(AttnStage);

    // issue loads for position p into stage s
    auto issue = [&](int p, int s) {
        const int pos = pos0 + p;
        const int n = pos >> 12;
        const int t = pos & (SKV - 1);
        const float* cqrow = (t & 1)
            ? (g_cond  + (size_t)(n * SQ + (t >> 1)) * EDIM)
            : (queries + (size_t)(n * SQ + (t >> 1)) * EDIM);
        const float* krow = keys   + (size_t)pos * EDIM;
        const float* vrow = values + (size_t)pos * EDIM;
        const int* mrow = mask + (size_t)pos * (HEADS * HEADS);

        uint32_t sb = sbase + s * stgsz;
        cp16(sb + (uint32_t)(offsetof(AttnStage, cq)) + tid * 16, cqrow + tid * 4);
        cp16(sb + (uint32_t)(offsetof(AttnStage, kv)) + (h * 17 + e) * 16, krow + tid * 4);
        cp16(sb + (uint32_t)(offsetof(AttnStage, vv)) + (h * 17 + e) * 16, vrow + tid * 4);
        if (tid < 64)
            cp16(sb + (uint32_t)(offsetof(AttnStage, msk)) + tid * 16, mrow + tid * 4);
        asm volatile("cp.async.commit_group;");
    };

    issue(0, 0);

    for (int p = 0; p < POS_PER_CTA; p++) {
        const int s = p & 1;
        if (p + 1 < POS_PER_CTA) {
            issue(p + 1, s ^ 1);
            asm volatile("cp.async.wait_group 1;");
        } else {
            asm volatile("cp.async.wait_group 0;");
        }
        __syncthreads();

        const AttnStage& st = stg[s];
        const int pos = pos0 + p;

        // scores
        float sc = 0.f;
        #pragma unroll
        for (int dv = 0; dv < 16; dv++) {
            float4 a = st.cq[h * 16 + dv];
            float4 b = st.kv[e * 17 + dv];
            sc += a.x * b.x + a.y * b.y + a.z * b.z + a.w * b.w;
        }
        sc *= 0.125f;
        if (st.msk[tid] == 0) sc = -1e20f;

        // group-of-16 softmax
        float mx = sc;
        #pragma unroll
        for (int m = 1; m < 16; m <<= 1)
            mx = fmaxf(mx, __shfl_xor_sync(0xffffffffu, mx, m));
        float pu = __expf(sc - mx);
        float den = pu;
        #pragma unroll
        for (int m = 1; m < 16; m <<= 1)
            den += __shfl_xor_sync(0xffffffffu, den, m);
        float prob = pu / den;

        // AV
        const int lanebase = (tid & 31) & 16;
        float4 acc = make_float4(0.f, 0.f, 0.f, 0.f);
        #pragma unroll
        for (int j = 0; j < 16; j++) {
            float a = __shfl_sync(0xffffffffu, prob, lanebase + j);
            float4 v = st.vv[j * 17 + e];
            acc.x += a * v.x;
            acc.y += a * v.y;
            acc.z += a * v.z;
            acc.w += a * v.w;
        }

        size_t base = (size_t)pos * EDIM + (size_t)tid * 4;
        *(__half2*)(g_aoh + base)     = __floats2half2_rn(acc.x, acc.y);
        *(__half2*)(g_aoh + base + 2) = __floats2half2_rn(acc.z, acc.w);

        __syncthreads();   // stage s free for reuse by issue(p+2)
    }
}

// ---------------------------------------------------------------------------
// Launch
// ---------------------------------------------------------------------------
extern "C" void kernel_launch(void* const* d_in, const int* in_sizes, int n_in,
                              void* d_out, int out_size)
{
    const float* values    = (const float*)d_in[0];
    const float* keys      = (const float*)d_in[1];
    const float* queries   = (const float*)d_in[2];
    const int*   mask      = (const int*)  d_in[3];
    const float* condition = (const float*)d_in[4];
    const float* Wc        = (const float*)d_in[5];
    const float* bc        = (const float*)d_in[6];
    const float* Wo        = (const float*)d_in[7];
    const float* bo        = (const float*)d_in[8];
    float* out = (float*)d_out;

    float* cond_ptr;
    __half *ch, *wch, *woh, *aoh;
    cudaGetSymbolAddress((void**)&cond_ptr, g_cond);
    cudaGetSymbolAddress((void**)&ch,  g_ch);
    cudaGetSymbolAddress((void**)&wch, g_wch);
    cudaGetSymbolAddress((void**)&woh, g_woh);
    cudaGetSymbolAddress((void**)&aoh, g_aoh);

    cudaFuncSetAttribute(gemm_hmma,
                         cudaFuncAttributeMaxDynamicSharedMemorySize, DSMEM);

    // fused converts (one launch)
    {
        int ntot = N_COND + N_WC + N_WO;
        to_half_all<<<ntot / 4 / 256, 256>>>(condition, ch, Wc, wch, Wo, woh);
    }

    // 1) cond = condition @ Wc^T + bc : M=8192, N=1024, K=512
    {
        dim3 grid(EDIM / BN, (NBATCH * SQ) / BM);
        gemm_hmma<<<grid, 128, DSMEM>>>(ch, wch, bc, cond_ptr,
                                        NBATCH * SQ, EDIM, CDIM);
    }

    // 2) attention -> g_aoh (fp16), pipelined
    attn_kernel<<<(NBATCH * SKV) / POS_PER_CTA, 256>>>(queries, keys, values, mask);

    // 3) out = attout @ Wo^T + bo : M=16384, N=1024, K=1024
    {
        dim3 grid(EDIM / BN, (NBATCH * SKV) / BM);
        gemm_hmma<<<grid, 128, DSMEM>>>(aoh, woh, bo, out,
                                        NBATCH * SKV, EDIM, EDIM);
    }
}

// round 15
// speedup vs baseline: 1.3826x; 1.2781x over previous
#include <cuda_runtime.h>
#include <cuda_fp16.h>
#include <stdint.h>
#include <math.h>

#define NBATCH 4
#define SQ    2048
#define SKV   4096
#define EDIM  1024
#define CDIM  512
#define HEADS 16
#define HDIM  64

// ---------------------------------------------------------------------------
// Static device scratch.
// ---------------------------------------------------------------------------
__device__ float  g_cond[(size_t)NBATCH * SQ * EDIM];      // fp32 cond (attn input)
__device__ __half g_ch[(size_t)NBATCH * SQ * CDIM];        // condition fp16
__device__ __half g_wch[(size_t)EDIM * CDIM];              // Wc fp16
__device__ __half g_woh[(size_t)EDIM * EDIM];              // Wo fp16
__device__ __half g_aoh[(size_t)NBATCH * SKV * EDIM];      // attn out fp16

// ---------------------------------------------------------------------------
// PTX helpers
// ---------------------------------------------------------------------------
__device__ __forceinline__ uint32_t smem_u32(const void* p) {
    uint32_t a;
    asm("{ .reg .u64 t; cvta.to.shared.u64 t, %1; cvt.u32.u64 %0, t; }"
        : "=r"(a) : "l"(p));
    return a;
}

__device__ __forceinline__ void cp16(uint32_t dst, const void* src) {
    asm volatile("cp.async.cg.shared.global [%0], [%1], 16;\n" :: "r"(dst), "l"(src));
}

#define LDSM4(r, addr) \
    asm volatile("ldmatrix.sync.aligned.m8n8.x4.shared.b16 {%0,%1,%2,%3}, [%4];" \
        : "=r"((r)[0]), "=r"((r)[1]), "=r"((r)[2]), "=r"((r)[3]) : "r"(addr))

#define LDSM4T(r, addr) \
    asm volatile("ldmatrix.sync.aligned.m8n8.x4.trans.shared.b16 {%0,%1,%2,%3}, [%4];" \
        : "=r"((r)[0]), "=r"((r)[1]), "=r"((r)[2]), "=r"((r)[3]) : "r"(addr))

#define MMA16816(d, a, b) \
    asm volatile("mma.sync.aligned.m16n8k16.row.col.f32.f16.f16.f32 " \
        "{%0,%1,%2,%3}, {%4,%5,%6,%7}, {%8,%9}, {%0,%1,%2,%3};" \
        : "+f"((d)[0]), "+f"((d)[1]), "+f"((d)[2]), "+f"((d)[3]) \
        : "r"((a)[0]), "r"((a)[1]), "r"((a)[2]), "r"((a)[3]), \
          "r"((b)[0]), "r"((b)[1]))

__device__ __forceinline__ uint32_t packh2(float a, float b) {
    __half2 h = __floats2half2_rn(a, b);
    return *(uint32_t*)&h;
}

// ---------------------------------------------------------------------------
// fused convert: fp32 -> fp16 for condition, Wc, Wo in one launch
// ---------------------------------------------------------------------------
#define N_COND (NBATCH * SQ * CDIM)
#define N_WC   (EDIM * CDIM)
#define N_WO   (EDIM * EDIM)

__global__ __launch_bounds__(256) void to_half_all(
    const float* __restrict__ s0, __half* __restrict__ d0,
    const float* __restrict__ s1, __half* __restrict__ d1,
    const float* __restrict__ s2, __half* __restrict__ d2)
{
    int i = (blockIdx.x * blockDim.x + threadIdx.x) * 4;
    const float* src;
    __half* dst;
    if (i < N_COND)                { src = s0;  dst = d0; }
    else if (i < N_COND + N_WC)    { src = s1 - N_COND; dst = d1 - N_COND; }
    else if (i < N_COND + N_WC + N_WO) {
        src = s2 - (N_COND + N_WC); dst = d2 - (N_COND + N_WC);
    } else return;
    float4 v = *(const float4*)(src + i);
    *(__half2*)(dst + i)     = __floats2half2_rn(v.x, v.y);
    *(__half2*)(dst + i + 2) = __floats2half2_rn(v.z, v.w);
}

// ---------------------------------------------------------------------------
// HMMA fp16 GEMM (unchanged from R13/R14).
// ---------------------------------------------------------------------------
#define BM 128
#define BN 128
#define BKC 64
#define AROW 144
#define ASTAGE (128 * AROW)
#define STAGE  (2 * ASTAGE)
#define NSTAGE 3
#define DSMEM  (NSTAGE * STAGE)

__device__ __forceinline__ void gemm_issue(
    uint32_t s0, int slot, int c, int K, int tid, int mBase, int nBase,
    const __half* __restrict__ A, const __half* __restrict__ B)
{
    int k0 = c * BKC;
    uint32_t sA = s0 + slot * STAGE;
    uint32_t sB = sA + ASTAGE;
    #pragma unroll
    for (int i = 0; i < 8; i++) {
        int ch = tid + i * 128;
        int r = ch >> 3, col = ch & 7;
        cp16(sA + r * AROW + col * 16, A + (size_t)(mBase + r) * K + k0 + col * 8);
        cp16(sB + r * AROW + col * 16, B + (size_t)(nBase + r) * K + k0 + col * 8);
    }
    asm volatile("cp.async.commit_group;");
}

__device__ __forceinline__ void load_a(
    uint32_t sA, int ks, int wm, int lane, uint32_t af[4][4])
{
    #pragma unroll
    for (int mi = 0; mi < 4; mi++) {
        uint32_t addr = sA + (wm + mi * 16 + (lane & 15)) * AROW
                      + ks * 32 + (lane >> 4) * 16;
        LDSM4(af[mi], addr);
    }
}

__device__ __forceinline__ void load_b_half(
    uint32_t sB, int ks, int wn, int lane, int h, uint32_t bf[4][2])
{
    #pragma unroll
    for (int p2 = 0; p2 < 2; p2++) {
        int p = h * 2 + p2;
        int grp = lane >> 3, w = lane & 7;
        int nsel = p * 2 + (grp >> 1);
        uint32_t addr = sB + (wn + nsel * 8 + w) * AROW
                      + ks * 32 + (grp & 1) * 16;
        uint32_t r[4];
        LDSM4(r, addr);
        bf[p2 * 2][0]     = r[0];
        bf[p2 * 2][1]     = r[1];
        bf[p2 * 2 + 1][0] = r[2];
        bf[p2 * 2 + 1][1] = r[3];
    }
}

__global__ __launch_bounds__(128, 2) void gemm_hmma(
    const __half* __restrict__ A, const __half* __restrict__ B,
    const float* __restrict__ bias, float* __restrict__ C,
    int M, int N, int K)
{
    extern __shared__ char smem[];
    const int tid  = threadIdx.x;
    const int wid  = tid >> 5;
    const int lane = tid & 31;
    const int mBase = blockIdx.y * BM;
    const int nBase = blockIdx.x * BN;
    const int wm = (wid & 1) * 64;
    const int wn = (wid >> 1) * 64;
    const int rot = (wid & 1) * 2;

    const uint32_t s0 = smem_u32(smem);
    const int NC = K / BKC;

    float acc[4][8][4];
    #pragma unroll
    for (int i = 0; i < 4; i++)
        #pragma unroll
        for (int j = 0; j < 8; j++)
            #pragma unroll
            for (int q = 0; q < 4; q++) acc[i][j][q] = 0.f;

    gemm_issue(s0, 0, 0, K, tid, mBase, nBase, A, B);
    gemm_issue(s0, 1, 1, K, tid, mBase, nBase, A, B);
    asm volatile("cp.async.wait_group 1;");
    __syncthreads();

    uint32_t af[2][4][4];
    load_a(s0, rot, wm, lane, af[0]);

    int buf = 0;
    for (int c = 0; c < NC; c++) {
        uint32_t csA = s0 + (c % NSTAGE) * STAGE;
        uint32_t csB = csA + ASTAGE;
        #pragma unroll
        for (int ksi = 0; ksi < 4; ksi++) {
            const int ksr = (ksi + rot) & 3;
            int nb = buf ^ 1;
            uint32_t bf0[4][2], bf1[4][2];
            load_b_half(csB, ksr, wn, lane, 0, bf0);
            load_b_half(csB, ksr, wn, lane, 1, bf1);

            if (ksi < 3) {
                load_a(csA, (ksi + 1 + rot) & 3, wm, lane, af[nb]);
            } else {
                if (c + 2 < NC)
                    gemm_issue(s0, (c + 2) % NSTAGE, c + 2, K, tid,
                               mBase, nBase, A, B);
                else
                    asm volatile("cp.async.commit_group;");
                if (c + 1 < NC) {
                    asm volatile("cp.async.wait_group 1;");
                    __syncthreads();
                    uint32_t nA = s0 + ((c + 1) % NSTAGE) * STAGE;
                    load_a(nA, rot, wm, lane, af[nb]);
                }
            }

            #pragma unroll
            for (int mi = 0; mi < 4; mi++)
                #pragma unroll
                for (int ni = 0; ni < 4; ni++)
                    MMA16816(acc[mi][ni], af[buf][mi], bf0[ni]);
            #pragma unroll
            for (int mi = 0; mi < 4; mi++)
                #pragma unroll
                for (int ni = 0; ni < 4; ni++)
                    MMA16816(acc[mi][ni + 4], af[buf][mi], bf1[ni]);

            buf = nb;
        }
    }

    const int g = lane >> 2, tg = lane & 3;
    #pragma unroll
    for (int mi = 0; mi < 4; mi++) {
        int row0 = mBase + wm + mi * 16 + g;
        #pragma unroll
        for (int ni = 0; ni < 8; ni++) {
            int col = nBase + wn + ni * 8 + tg * 2;
            float b0 = __ldg(bias + col), b1 = __ldg(bias + col + 1);
            float2 v0 = make_float2(acc[mi][ni][0] + b0, acc[mi][ni][1] + b1);
            float2 v1 = make_float2(acc[mi][ni][2] + b0, acc[mi][ni][3] + b1);
            *(float2*)(C + (size_t)row0 * N + col) = v0;
            *(float2*)(C + (size_t)(row0 + 8) * N + col) = v1;
        }
    }
}

// ---------------------------------------------------------------------------
// MMA attention. Pipelined fp32 staging (as R14); per position: cooperative
// fp32->fp16 convert into 144B-stride rows, then warp 0 computes the whole
// position with 16 HMMAs. Score C-frag layout == AV A-operand layout, so
// softmax is done in-fragment (2 shfl_xor within lane quads).
// ---------------------------------------------------------------------------
#define POS_PER_CTA 8
#define HROW 72   // fp16 row stride in halves (144B)

struct AttnStage {
    float4 cq[256];        // [h*16 + dv]
    float4 kv[16 * 17];    // [e*17 + dv]
    float4 vv[16 * 17];    // [e*17 + dv]
    int    msk[256];       // [h*16 + e]
};

__global__ __launch_bounds__(256) void attn_kernel(
    const float* __restrict__ queries, const float* __restrict__ keys,
    const float* __restrict__ values, const int* __restrict__ mask)
{
    __shared__ AttnStage stg[2];
    __shared__ __half cqh[16 * HROW];
    __shared__ __half kh[16 * HROW];
    __shared__ __half vh[16 * HROW];
    __shared__ __half outh[1024];

    const int tid = threadIdx.x;
    const int wid = tid >> 5;
    const int lane = tid & 31;
    const int h = tid >> 4;
    const int e = tid & 15;
    const int pos0 = blockIdx.x * POS_PER_CTA;

    const uint32_t sbase = smem_u32(&stg[0]);
    const uint32_t stgsz = (uint32_t)sizeof(AttnStage);
    const uint32_t cqh_a = smem_u32(cqh);
    const uint32_t kh_a  = smem_u32(kh);
    const uint32_t vh_a  = smem_u32(vh);

    auto issue = [&](int p, int s) {
        const int pos = pos0 + p;
        const int n = pos >> 12;
        const int t = pos & (SKV - 1);
        const float* cqrow = (t & 1)
            ? (g_cond  + (size_t)(n * SQ + (t >> 1)) * EDIM)
            : (queries + (size_t)(n * SQ + (t >> 1)) * EDIM);
        const float* krow = keys   + (size_t)pos * EDIM;
        const float* vrow = values + (size_t)pos * EDIM;
        const int* mrow = mask + (size_t)pos * (HEADS * HEADS);

        uint32_t sb = sbase + s * stgsz;
        cp16(sb + (uint32_t)(offsetof(AttnStage, cq)) + tid * 16, cqrow + tid * 4);
        cp16(sb + (uint32_t)(offsetof(AttnStage, kv)) + (h * 17 + e) * 16, krow + tid * 4);
        cp16(sb + (uint32_t)(offsetof(AttnStage, vv)) + (h * 17 + e) * 16, vrow + tid * 4);
        if (tid < 64)
            cp16(sb + (uint32_t)(offsetof(AttnStage, msk)) + tid * 16, mrow + tid * 4);
        asm volatile("cp.async.commit_group;");
    };

    issue(0, 0);

    for (int p = 0; p < POS_PER_CTA; p++) {
        const int s = p & 1;
        if (p + 1 < POS_PER_CTA) {
            issue(p + 1, s ^ 1);
            asm volatile("cp.async.wait_group 1;");
        } else {
            asm volatile("cp.async.wait_group 0;");
        }
        __syncthreads();                     // fp32 stage s ready

        const AttnStage& st = stg[s];
        const int pos = pos0 + p;

        // cooperative fp32 -> fp16 convert into 144B-stride rows
        {
            float4 q = st.cq[tid];           // row h, dims e*4..e*4+3
            uint2 qp = make_uint2(packh2(q.x, q.y), packh2(q.z, q.w));
            *(uint2*)&cqh[h * HROW + e * 4] = qp;

            float4 k = st.kv[h * 17 + e];    // row h(=e-row), dims e*4..
            uint2 kp = make_uint2(packh2(k.x, k.y), packh2(k.z, k.w));
            *(uint2*)&kh[h * HROW + e * 4] = kp;

            float4 v = st.vv[h * 17 + e];
            uint2 vp = make_uint2(packh2(v.x, v.y), packh2(v.z, v.w));
            *(uint2*)&vh[h * HROW + e * 4] = vp;
        }
        __syncthreads();                     // fp16 ready

        if (wid == 0) {
            // ---- scores: C[16x16] = cq(16x64) @ K(16x64)^T, fp32 accum ----
            float C1[4] = {0.f, 0.f, 0.f, 0.f};
            float C2[4] = {0.f, 0.f, 0.f, 0.f};
            #pragma unroll
            for (int ks = 0; ks < 4; ks++) {
                uint32_t a[4], b[4];
                LDSM4(a, cqh_a + (lane & 15) * 144 + ks * 32 + (lane >> 4) * 16);
                LDSM4(b, kh_a + ((lane >> 4) * 8 + (lane & 7)) * 144
                             + ks * 32 + ((lane >> 3) & 1) * 16);
                MMA16816(C1, a, b);
                MMA16816(C2, a, b + 2);
            }

            // ---- softmax in fragment layout ----
            const int g = lane >> 2, tg = lane & 3;
            float sc[8];
            sc[0] = C1[0]; sc[1] = C1[1]; sc[2] = C1[2]; sc[3] = C1[3];
            sc[4] = C2[0]; sc[5] = C2[1]; sc[6] = C2[2]; sc[7] = C2[3];
            // i: {0,1}=row g cols 2tg,2tg+1 ; {2,3}=row g+8 ; {4..7}=cols+8
            #pragma unroll
            for (int i = 0; i < 8; i++) {
                int row = g + ((i >> 1) & 1) * 8;
                int col = 2 * tg + (i & 1) + (i >= 4 ? 8 : 0);
                float v = sc[i] * 0.125f;
                if (st.msk[row * 16 + col] == 0) v = -1e20f;
                sc[i] = v;
            }
            float mxA = fmaxf(fmaxf(sc[0], sc[1]), fmaxf(sc[4], sc[5]));
            float mxB = fmaxf(fmaxf(sc[2], sc[3]), fmaxf(sc[6], sc[7]));
            #pragma unroll
            for (int m = 1; m < 4; m <<= 1) {
                mxA = fmaxf(mxA, __shfl_xor_sync(0xffffffffu, mxA, m));
                mxB = fmaxf(mxB, __shfl_xor_sync(0xffffffffu, mxB, m));
            }
            float ex[8];
            ex[0] = __expf(sc[0] - mxA); ex[1] = __expf(sc[1] - mxA);
            ex[4] = __expf(sc[4] - mxA); ex[5] = __expf(sc[5] - mxA);
            ex[2] = __expf(sc[2] - mxB); ex[3] = __expf(sc[3] - mxB);
            ex[6] = __expf(sc[6] - mxB); ex[7] = __expf(sc[7] - mxB);
            float dA = ex[0] + ex[1] + ex[4] + ex[5];
            float dB = ex[2] + ex[3] + ex[6] + ex[7];
            #pragma unroll
            for (int m = 1; m < 4; m <<= 1) {
                dA += __shfl_xor_sync(0xffffffffu, dA, m);
                dB += __shfl_xor_sync(0xffffffffu, dB, m);
            }
            float rA = __frcp_rn(dA), rB = __frcp_rn(dB);

            // P fragment -> AV A-operand (register-for-register)
            uint32_t pa[4];
            pa[0] = packh2(ex[0] * rA, ex[1] * rA);
            pa[1] = packh2(ex[2] * rB, ex[3] * rB);
            pa[2] = packh2(ex[4] * rA, ex[5] * rA);
            pa[3] = packh2(ex[6] * rB, ex[7] * rB);

            // ---- AV: out(16x64) = P(16x16) @ V(16x64), B via ldmatrix.trans ----
            #pragma unroll
            for (int cp2 = 0; cp2 < 4; cp2++) {
                int c = cp2 * 2;
                uint32_t b[4];
                LDSM4T(b, vh_a + (lane & 15) * 144 + (c + (lane >> 4)) * 16);
                float O1[4] = {0.f, 0.f, 0.f, 0.f};
                float O2[4] = {0.f, 0.f, 0.f, 0.f};
                MMA16816(O1, pa, b);
                MMA16816(O2, pa, b + 2);
                *(__half2*)&outh[g * 64 + c * 8 + 2 * tg]
                    = __floats2half2_rn(O1[0], O1[1]);
                *(__half2*)&outh[(g + 8) * 64 + c * 8 + 2 * tg]
                    = __floats2half2_rn(O1[2], O1[3]);
                *(__half2*)&outh[g * 64 + (c + 1) * 8 + 2 * tg]
                    = __floats2half2_rn(O2[0], O2[1]);
                *(__half2*)&outh[(g + 8) * 64 + (c + 1) * 8 + 2 * tg]
                    = __floats2half2_rn(O2[2], O2[3]);
            }
        }
        __syncthreads();                     // outh ready, fp16 region free

        // cooperative coalesced store
        {
            uint2 val = *(uint2*)&outh[tid * 4];
            *(uint2*)(g_aoh + (size_t)pos * EDIM + tid * 4) = val;
        }
        __syncthreads();                     // stage s free
    }
}

// ---------------------------------------------------------------------------
// Launch
// ---------------------------------------------------------------------------
extern "C" void kernel_launch(void* const* d_in, const int* in_sizes, int n_in,
                              void* d_out, int out_size)
{
    const float* values    = (const float*)d_in[0];
    const float* keys      = (const float*)d_in[1];
    const float* queries   = (const float*)d_in[2];
    const int*   mask      = (const int*)  d_in[3];
    const float* condition = (const float*)d_in[4];
    const float* Wc        = (const float*)d_in[5];
    const float* bc        = (const float*)d_in[6];
    const float* Wo        = (const float*)d_in[7];
    const float* bo        = (const float*)d_in[8];
    float* out = (float*)d_out;

    float* cond_ptr;
    __half *ch, *wch, *woh, *aoh;
    cudaGetSymbolAddress((void**)&cond_ptr, g_cond);
    cudaGetSymbolAddress((void**)&ch,  g_ch);
    cudaGetSymbolAddress((void**)&wch, g_wch);
    cudaGetSymbolAddress((void**)&woh, g_woh);
    cudaGetSymbolAddress((void**)&aoh, g_aoh);

    cudaFuncSetAttribute(gemm_hmma,
                         cudaFuncAttributeMaxDynamicSharedMemorySize, DSMEM);

    // fused converts (one launch)
    {
        int ntot = N_COND + N_WC + N_WO;
        to_half_all<<<ntot / 4 / 256, 256>>>(condition, ch, Wc, wch, Wo, woh);
    }

    // 1) cond = condition @ Wc^T + bc : M=8192, N=1024, K=512
    {
        dim3 grid(EDIM / BN, (NBATCH * SQ) / BM);
        gemm_hmma<<<grid, 128, DSMEM>>>(ch, wch, bc, cond_ptr,
                                        NBATCH * SQ, EDIM, CDIM);
    }

    // 2) attention -> g_aoh (fp16), MMA per position
    attn_kernel<<<(NBATCH * SKV) / POS_PER_CTA, 256>>>(queries, keys, values, mask);

    // 3) out = attout @ Wo^T + bo : M=16384, N=1024, K=1024
    {
        dim3 grid(EDIM / BN, (NBATCH * SKV) / BM);
        gemm_hmma<<<grid, 128, DSMEM>>>(aoh, woh, bo, out,
                                        NBATCH * SKV, EDIM, EDIM);
    }
}